// round 2
// baseline (speedup 1.0000x reference)
#include <cuda_runtime.h>
#include <math.h>

// Problem constants (from reference setup_inputs)
#define BB 2
#define HH 256
#define WW 256
#define DD 128
#define D3 (DD * DD * DD)
#define DT 0.03125f
#define NSTEPS 111

// Scratch: channel-interleaved volume [B, D, D, D, 4] as float4. 64 MB.
__device__ float4 g_vol[BB * D3];

// ---------------------------------------------------------------------------
// Pass 1: interleave volume channels.  in: [B, 4, D, D, D]  out: [B, D^3] f4
// ---------------------------------------------------------------------------
__global__ void interleave_kernel(const float* __restrict__ vol) {
    long i = (long)blockIdx.x * blockDim.x + threadIdx.x;
    if (i >= (long)BB * D3) return;
    int b = (int)(i / D3);
    int s = (int)(i % D3);
    const float* base = vol + (long)b * 4 * D3 + s;
    g_vol[i] = make_float4(base[0], base[D3], base[2 * D3], base[3 * D3]);
}

// ---------------------------------------------------------------------------
// Trilinear sample of interleaved volume (smooth: FMA contraction harmless)
// ---------------------------------------------------------------------------
__device__ __forceinline__ float4 f4_lerp(float4 a, float4 b, float t) {
    return make_float4(a.x + (b.x - a.x) * t,
                       a.y + (b.y - a.y) * t,
                       a.z + (b.z - a.z) * t,
                       a.w + (b.w - a.w) * t);
}

__device__ __forceinline__ float4 trilerp(const float4* __restrict__ vb,
                                          float px, float py, float pz) {
    const float scale = 0.5f * (float)(DD - 1);
    float gx = fminf(fmaxf((px + 1.0f) * scale, 0.0f), (float)(DD - 1));
    float gy = fminf(fmaxf((py + 1.0f) * scale, 0.0f), (float)(DD - 1));
    float gz = fminf(fmaxf((pz + 1.0f) * scale, 0.0f), (float)(DD - 1));
    int x0 = min((int)gx, DD - 2);
    int y0 = min((int)gy, DD - 2);
    int z0 = min((int)gz, DD - 2);
    float fx = gx - (float)x0;
    float fy = gy - (float)y0;
    float fz = gz - (float)z0;

    int i000 = (z0 * DD + y0) * DD + x0;
    const float4* p0 = vb + i000;
    float4 v000 = __ldg(p0);
    float4 v001 = __ldg(p0 + 1);
    float4 v010 = __ldg(p0 + DD);
    float4 v011 = __ldg(p0 + DD + 1);
    const float4* p1 = p0 + DD * DD;
    float4 v100 = __ldg(p1);
    float4 v101 = __ldg(p1 + 1);
    float4 v110 = __ldg(p1 + DD);
    float4 v111 = __ldg(p1 + DD + 1);

    float4 c00 = f4_lerp(v000, v001, fx);
    float4 c01 = f4_lerp(v010, v011, fx);
    float4 c10 = f4_lerp(v100, v101, fx);
    float4 c11 = f4_lerp(v110, v111, fx);
    float4 c0 = f4_lerp(c00, c01, fy);
    float4 c1 = f4_lerp(c10, c11, fy);
    return f4_lerp(c0, c1, fz);
}

// ---------------------------------------------------------------------------
// Pass 2: ray march. One thread per pixel.
// Ray setup + position stepping replicate the reference's IEEE fp32 ops
// bit-exactly (unfused _rn intrinsics) because step-0 validity is a
// knife-edge: the entry position lies exactly on the cube face.
// ---------------------------------------------------------------------------
__global__ void raymarch_kernel(const float* __restrict__ camrot,
                                const float* __restrict__ campos,
                                const float* __restrict__ focal,
                                const float* __restrict__ princpt,
                                const float* __restrict__ pixelcoords,
                                float* __restrict__ out) {
    int x = blockIdx.x * blockDim.x + threadIdx.x;
    int y = blockIdx.y * blockDim.y + threadIdx.y;
    int b = blockIdx.z;
    if (x >= WW || y >= HH) return;

    // --- camera ray (bit-exact vs reference) ---
    long pidx = (((long)b * HH + y) * WW + x) * 2;
    float px = pixelcoords[pidx + 0];
    float py = pixelcoords[pidx + 1];
    float rx = __fdiv_rn(__fsub_rn(px, princpt[b * 2 + 0]), focal[b * 2 + 0]);
    float ry = __fdiv_rn(__fsub_rn(py, princpt[b * 2 + 1]), focal[b * 2 + 1]);
    float rz = 1.0f;
    // einsum with camrot: dir_j = sum_i R[i][j] * r_i  (in i order)
    const float* R = camrot + b * 9;
    float dx = __fadd_rn(__fadd_rn(__fmul_rn(R[0], rx), __fmul_rn(R[3], ry)),
                         __fmul_rn(R[6], rz));
    float dy = __fadd_rn(__fadd_rn(__fmul_rn(R[1], rx), __fmul_rn(R[4], ry)),
                         __fmul_rn(R[7], rz));
    float dz = __fadd_rn(__fadd_rn(__fmul_rn(R[2], rx), __fmul_rn(R[5], ry)),
                         __fmul_rn(R[8], rz));
    // norm: ((dx^2 + dy^2) + dz^2), sqrt, true division
    float n2 = __fadd_rn(__fadd_rn(__fmul_rn(dx, dx), __fmul_rn(dy, dy)),
                         __fmul_rn(dz, dz));
    float nrm = sqrtf(n2);
    dx = __fdiv_rn(dx, nrm);
    dy = __fdiv_rn(dy, nrm);
    dz = __fdiv_rn(dz, nrm);

    float cx = campos[b * 3 + 0];
    float cy = campos[b * 3 + 1];
    float cz = campos[b * 3 + 2];

    // --- AABB [-1,1]^3 intersection (IEEE divisions; inf semantics ok) ---
    float t1x = __fdiv_rn(__fsub_rn(-1.0f, cx), dx);
    float t2x = __fdiv_rn(__fsub_rn( 1.0f, cx), dx);
    float t1y = __fdiv_rn(__fsub_rn(-1.0f, cy), dy);
    float t2y = __fdiv_rn(__fsub_rn( 1.0f, cy), dy);
    float t1z = __fdiv_rn(__fsub_rn(-1.0f, cz), dz);
    float t2z = __fdiv_rn(__fsub_rn( 1.0f, cz), dz);
    float tmin = fmaxf(fminf(t1x, t2x), fmaxf(fminf(t1y, t2y), fminf(t1z, t2z)));
    float tmax = fminf(fmaxf(t1x, t2x), fminf(fmaxf(t1y, t2y), fmaxf(t1z, t2z)));
    bool hit = tmin < tmax;
    float t0 = fmaxf(hit ? tmin : 0.0f, 0.0f);

    // raypos = campos + raydir * t0 (unfused, matches reference rounding)
    float posx = __fadd_rn(cx, __fmul_rn(dx, t0));
    float posy = __fadd_rn(cy, __fmul_rn(dy, t0));
    float posz = __fadd_rn(cz, __fmul_rn(dz, t0));

    // per-step increment raydir*DT (reference recomputes; same rounded value)
    float sx = __fmul_rn(dx, DT);
    float sy = __fmul_rn(dy, DT);
    float sz = __fmul_rn(dz, DT);

    float r_out = 0.0f, g_out = 0.0f, b_out = 0.0f, a_out = 0.0f;

    const float4* vb = g_vol + (long)b * D3;
    // conservative exit bound: after t exceeds tmax + 2*DT no step can be valid
    float t_stop = hit ? (tmax + 2.0f * DT) : -1.0f;
    float t = t0;

    #pragma unroll 1
    for (int k = 0; k < NSTEPS; k++) {
        if (t > t_stop) break;           // ray exited cube (or never hit)
        bool valid = (posx > -1.0f) & (posx < 1.0f) &
                     (posy > -1.0f) & (posy < 1.0f) &
                     (posz > -1.0f) & (posz < 1.0f);
        if (valid) {
            float4 s = trilerp(vb, posx, posy, posz);
            float contrib = __fsub_rn(fminf(__fadd_rn(a_out, __fmul_rn(s.w, DT)), 1.0f), a_out);
            r_out = __fadd_rn(r_out, __fmul_rn(s.x, contrib));
            g_out = __fadd_rn(g_out, __fmul_rn(s.y, contrib));
            b_out = __fadd_rn(b_out, __fmul_rn(s.z, contrib));
            a_out = __fadd_rn(a_out, contrib);
            if (a_out >= 1.0f) break;    // saturated: future contribs exactly 0
        }
        posx = __fadd_rn(posx, sx);
        posy = __fadd_rn(posy, sy);
        posz = __fadd_rn(posz, sz);
        t += DT;
    }

    long obase = (((long)b * 4) * HH + y) * WW + x;
    const long cstride = (long)HH * WW;
    out[obase + 0 * cstride] = r_out;
    out[obase + 1 * cstride] = g_out;
    out[obase + 2 * cstride] = b_out;
    out[obase + 3 * cstride] = a_out;
}

extern "C" void kernel_launch(void* const* d_in, const int* in_sizes, int n_in,
                              void* d_out, int out_size) {
    const float* camrot      = (const float*)d_in[0];
    const float* campos      = (const float*)d_in[1];
    const float* focal       = (const float*)d_in[2];
    const float* princpt     = (const float*)d_in[3];
    const float* pixelcoords = (const float*)d_in[4];
    const float* volume      = (const float*)d_in[5];
    float* out = (float*)d_out;

    {
        long n = (long)BB * D3;
        int threads = 256;
        int blocks = (int)((n + threads - 1) / threads);
        interleave_kernel<<<blocks, threads>>>(volume);
    }
    {
        dim3 block(16, 16, 1);
        dim3 grid(WW / 16, HH / 16, BB);
        raymarch_kernel<<<grid, block>>>(camrot, campos, focal, princpt,
                                         pixelcoords, out);
    }
}

// round 3
// speedup vs baseline: 1.4299x; 1.4299x over previous
#include <cuda_runtime.h>
#include <math.h>

// Problem constants (from reference setup_inputs)
#define BB 2
#define HH 256
#define WW 256
#define DD 128
#define D3 (DD * DD * DD)
#define DT 0.03125f
#define NSTEPS 111

// Scratch: channel-interleaved volume [B, D, D, D, 4] as float4. 64 MB.
__device__ float4 g_vol[BB * D3];

// ---------------------------------------------------------------------------
// Pass 1: interleave volume channels.  in: [B, 4, D, D, D]  out: [B, D^3] f4
// ---------------------------------------------------------------------------
__global__ void interleave_kernel(const float* __restrict__ vol) {
    long i = (long)blockIdx.x * blockDim.x + threadIdx.x;
    if (i >= (long)BB * D3) return;
    int b = (int)(i / D3);
    int s = (int)(i % D3);
    const float* base = vol + (long)b * 4 * D3 + s;
    g_vol[i] = make_float4(base[0], base[D3], base[2 * D3], base[3 * D3]);
}

// ---------------------------------------------------------------------------
// Pass 2: ray march. One thread per pixel, 16x8 tiles.
// Ray setup + position stepping replicate the reference's IEEE fp32 ops
// bit-exactly (unfused _rn intrinsics): step-0 validity is a knife-edge
// (entry position lies exactly on the cube face). Everything downstream of a
// valid position is smooth, so FMA contraction there is harmless.
// ---------------------------------------------------------------------------
__global__ void __launch_bounds__(128, 8)
raymarch_kernel(const float* __restrict__ camrot,
                const float* __restrict__ campos,
                const float* __restrict__ focal,
                const float* __restrict__ princpt,
                const float* __restrict__ pixelcoords,
                float* __restrict__ out) {
    int x = blockIdx.x * blockDim.x + threadIdx.x;
    int y = blockIdx.y * blockDim.y + threadIdx.y;
    int b = blockIdx.z;

    // --- camera ray (bit-exact vs reference) ---
    long pidx = (((long)b * HH + y) * WW + x) * 2;
    float px = pixelcoords[pidx + 0];
    float py = pixelcoords[pidx + 1];
    float rx = __fdiv_rn(__fsub_rn(px, princpt[b * 2 + 0]), focal[b * 2 + 0]);
    float ry = __fdiv_rn(__fsub_rn(py, princpt[b * 2 + 1]), focal[b * 2 + 1]);
    float rz = 1.0f;
    const float* R = camrot + b * 9;  // dir_j = sum_i R[i][j] * r_i
    float dx = __fadd_rn(__fadd_rn(__fmul_rn(R[0], rx), __fmul_rn(R[3], ry)),
                         __fmul_rn(R[6], rz));
    float dy = __fadd_rn(__fadd_rn(__fmul_rn(R[1], rx), __fmul_rn(R[4], ry)),
                         __fmul_rn(R[7], rz));
    float dz = __fadd_rn(__fadd_rn(__fmul_rn(R[2], rx), __fmul_rn(R[5], ry)),
                         __fmul_rn(R[8], rz));
    float n2 = __fadd_rn(__fadd_rn(__fmul_rn(dx, dx), __fmul_rn(dy, dy)),
                         __fmul_rn(dz, dz));
    float nrm = sqrtf(n2);
    dx = __fdiv_rn(dx, nrm);
    dy = __fdiv_rn(dy, nrm);
    dz = __fdiv_rn(dz, nrm);

    float cx = campos[b * 3 + 0];
    float cy = campos[b * 3 + 1];
    float cz = campos[b * 3 + 2];

    // --- AABB [-1,1]^3 intersection (IEEE divisions; inf semantics ok) ---
    float t1x = __fdiv_rn(__fsub_rn(-1.0f, cx), dx);
    float t2x = __fdiv_rn(__fsub_rn( 1.0f, cx), dx);
    float t1y = __fdiv_rn(__fsub_rn(-1.0f, cy), dy);
    float t2y = __fdiv_rn(__fsub_rn( 1.0f, cy), dy);
    float t1z = __fdiv_rn(__fsub_rn(-1.0f, cz), dz);
    float t2z = __fdiv_rn(__fsub_rn( 1.0f, cz), dz);
    float tmin = fmaxf(fminf(t1x, t2x), fmaxf(fminf(t1y, t2y), fminf(t1z, t2z)));
    float tmax = fminf(fmaxf(t1x, t2x), fminf(fmaxf(t1y, t2y), fmaxf(t1z, t2z)));
    bool hit = tmin < tmax;
    float t0 = fmaxf(hit ? tmin : 0.0f, 0.0f);

    // raypos = campos + raydir * t0 (unfused, matches reference rounding)
    float posx = __fadd_rn(cx, __fmul_rn(dx, t0));
    float posy = __fadd_rn(cy, __fmul_rn(dy, t0));
    float posz = __fadd_rn(cz, __fmul_rn(dz, t0));

    // per-step increment raydir*DT (reference recomputes; same rounded value)
    float sx = __fmul_rn(dx, DT);
    float sy = __fmul_rn(dy, DT);
    float sz = __fmul_rn(dz, DT);

    float r_out = 0.0f, g_out = 0.0f, b_out = 0.0f, a_out = 0.0f;

    if (hit) {
        const float4* __restrict__ vb = g_vol + (long)b * D3;
        float t_stop = tmax + 2.0f * DT;  // beyond this, every step is invalid
        float t = t0;
        bool valid = (posx > -1.0f) & (posx < 1.0f) &
                     (posy > -1.0f) & (posy < 1.0f) &
                     (posz > -1.0f) & (posz < 1.0f);

        #pragma unroll 1
        for (int k = 0; k < NSTEPS; k++) {
            if (valid) {
                // grid coords (smooth path; clamps dead since pos in (-1,1))
                float gx = fmaf(posx, 63.5f, 63.5f);
                float gy = fmaf(posy, 63.5f, 63.5f);
                float gz = fmaf(posz, 63.5f, 63.5f);
                int x0 = min((int)gx, DD - 2);
                int y0 = min((int)gy, DD - 2);
                int z0 = min((int)gz, DD - 2);
                int i000 = (z0 << 14) + (y0 << 7) + x0;
                const float4* p0 = vb + i000;
                // issue all 8 loads up front (MLP=8)
                float4 v000 = __ldg(p0);
                float4 v001 = __ldg(p0 + 1);
                float4 v010 = __ldg(p0 + DD);
                float4 v011 = __ldg(p0 + DD + 1);
                float4 v100 = __ldg(p0 + DD * DD);
                float4 v101 = __ldg(p0 + DD * DD + 1);
                float4 v110 = __ldg(p0 + DD * DD + DD);
                float4 v111 = __ldg(p0 + DD * DD + DD + 1);

                // load-independent work overlaps the load latency:
                float fx = gx - (float)x0;
                float fy = gy - (float)y0;
                float fz = gz - (float)z0;
                float wx0 = 1.0f - fx;
                float wy0 = 1.0f - fy;
                float wz0 = 1.0f - fz;
                float w00 = wz0 * wy0, w01 = wz0 * fy;
                float w10 = fz * wy0,  w11 = fz * fy;
                float w000 = w00 * wx0, w001 = w00 * fx;
                float w010 = w01 * wx0, w011 = w01 * fx;
                float w100 = w10 * wx0, w101 = w10 * fx;
                float w110 = w11 * wx0, w111 = w11 * fx;

                // 32 independent FMAs consume the loads
                float s0, s1, s2, s3;
                s0 = w000 * v000.x; s1 = w000 * v000.y;
                s2 = w000 * v000.z; s3 = w000 * v000.w;
                s0 = fmaf(w001, v001.x, s0); s1 = fmaf(w001, v001.y, s1);
                s2 = fmaf(w001, v001.z, s2); s3 = fmaf(w001, v001.w, s3);
                s0 = fmaf(w010, v010.x, s0); s1 = fmaf(w010, v010.y, s1);
                s2 = fmaf(w010, v010.z, s2); s3 = fmaf(w010, v010.w, s3);
                s0 = fmaf(w011, v011.x, s0); s1 = fmaf(w011, v011.y, s1);
                s2 = fmaf(w011, v011.z, s2); s3 = fmaf(w011, v011.w, s3);
                s0 = fmaf(w100, v100.x, s0); s1 = fmaf(w100, v100.y, s1);
                s2 = fmaf(w100, v100.z, s2); s3 = fmaf(w100, v100.w, s3);
                s0 = fmaf(w101, v101.x, s0); s1 = fmaf(w101, v101.y, s1);
                s2 = fmaf(w101, v101.z, s2); s3 = fmaf(w101, v101.w, s3);
                s0 = fmaf(w110, v110.x, s0); s1 = fmaf(w110, v110.y, s1);
                s2 = fmaf(w110, v110.z, s2); s3 = fmaf(w110, v110.w, s3);
                s0 = fmaf(w111, v111.x, s0); s1 = fmaf(w111, v111.y, s1);
                s2 = fmaf(w111, v111.z, s2); s3 = fmaf(w111, v111.w, s3);

                float contrib = __fsub_rn(
                    fminf(__fadd_rn(a_out, __fmul_rn(s3, DT)), 1.0f), a_out);
                r_out = __fadd_rn(r_out, __fmul_rn(s0, contrib));
                g_out = __fadd_rn(g_out, __fmul_rn(s1, contrib));
                b_out = __fadd_rn(b_out, __fmul_rn(s2, contrib));
                a_out = __fadd_rn(a_out, contrib);
                if (a_out >= 1.0f) break;  // saturated: future contribs are 0
            }
            // exact position advance (knife-edge-sensitive)
            posx = __fadd_rn(posx, sx);
            posy = __fadd_rn(posy, sy);
            posz = __fadd_rn(posz, sz);
            t += DT;
            if (t > t_stop) break;         // exited cube: all future invalid
            valid = (posx > -1.0f) & (posx < 1.0f) &
                    (posy > -1.0f) & (posy < 1.0f) &
                    (posz > -1.0f) & (posz < 1.0f);
        }
    }

    long obase = (((long)b * 4) * HH + y) * WW + x;
    const long cstride = (long)HH * WW;
    out[obase + 0 * cstride] = r_out;
    out[obase + 1 * cstride] = g_out;
    out[obase + 2 * cstride] = b_out;
    out[obase + 3 * cstride] = a_out;
}

extern "C" void kernel_launch(void* const* d_in, const int* in_sizes, int n_in,
                              void* d_out, int out_size) {
    const float* camrot      = (const float*)d_in[0];
    const float* campos      = (const float*)d_in[1];
    const float* focal       = (const float*)d_in[2];
    const float* princpt     = (const float*)d_in[3];
    const float* pixelcoords = (const float*)d_in[4];
    const float* volume      = (const float*)d_in[5];
    float* out = (float*)d_out;

    {
        long n = (long)BB * D3;
        int threads = 256;
        int blocks = (int)((n + threads - 1) / threads);
        interleave_kernel<<<blocks, threads>>>(volume);
    }
    {
        dim3 block(16, 8, 1);
        dim3 grid(WW / 16, HH / 8, BB);
        raymarch_kernel<<<grid, block>>>(camrot, campos, focal, princpt,
                                         pixelcoords, out);
    }
}